// round 9
// baseline (speedup 1.0000x reference)
#include <cuda_runtime.h>
#include <cuda_bf16.h>
#include <math.h>
#include <float.h>

// Problem constants
#define BATCH 2
#define TT    8
#define NN    10000
#define DD    128
#define EE    320000
#define LL    2
#define G3    384
#define ETOT  (EE + NN)   // edges + self loops

#define CDIV(a,b) (((a)+(b)-1)/(b))

// ---------------- scratch (device globals; no allocations allowed) ----------------
__device__ float g_px [TT * BATCH * NN * DD]; // propagated x, all timesteps  [t][b][n][d]
__device__ float g_pa [BATCH * NN * DD];      // propagated act_7
__device__ float g_act[BATCH * NN * DD];      // layer-0 activation output
__device__ float g_W  [LL * BATCH * DD * DD]; // evolving weights, layout [c][b][i][j]
__device__ float g_wihT[LL * DD * G3];        // transposed GRU weights [c][k][q]
__device__ float g_whhT[LL * DD * G3];
__device__ float g_deg[NN];                   // degree, then dinv in-place
__device__ int   g_cnt[NN];
__device__ int   g_indptr[NN + 1];
__device__ int   g_cursor[NN];
__device__ int   g_src[ETOT];
__device__ int   g_tgt[ETOT];
__device__ float g_wn [ETOT];
__device__ int   g_bsrc[ETOT];                // CSR-bucketed sources
__device__ float g_bw  [ETOT];                // CSR-bucketed normalized weights
__device__ float g_sc0[TT * BATCH * NN];      // layer-0 scores, all t
__device__ float g_sc1[BATCH * NN];           // layer-1 scores (current t)
__device__ int   g_ti0[TT * BATCH * DD];
__device__ float g_tv0[TT * BATCH * DD];
__device__ int   g_ti1[BATCH * DD];
__device__ float g_tv1[BATCH * DD];
__device__ int   g_is64;

// ---------------- preprocessing kernels ----------------

__global__ void k_detect(const void* ei) {
    __shared__ int flag;
    if (threadIdx.x == 0) flag = 0;
    __syncthreads();
    const int* w = (const int*)ei;
    for (int i = threadIdx.x; i < 1024; i += blockDim.x) {
        if (w[2 * i + 1] != 0) flag = 1;
    }
    __syncthreads();
    if (threadIdx.x == 0) g_is64 = flag ? 0 : 1;
}

__global__ void k_zero() {
    int i = blockIdx.x * blockDim.x + threadIdx.x;
    if (i < NN) { g_deg[i] = 0.f; g_cnt[i] = 0; }
}

__global__ void k_convert(const void* ei) {
    int e = blockIdx.x * blockDim.x + threadIdx.x;
    if (e >= ETOT) return;
    int s, t;
    if (e < EE) {
        if (g_is64) {
            const long long* p = (const long long*)ei;
            s = (int)p[e]; t = (int)p[EE + e];
        } else {
            const int* p = (const int*)ei;
            s = p[e]; t = p[EE + e];
        }
    } else {
        s = t = e - EE;  // self loop
    }
    g_src[e] = s; g_tgt[e] = t;
}

__global__ void k_deg(const float* __restrict__ ew) {
    int e = blockIdx.x * blockDim.x + threadIdx.x;
    if (e >= ETOT) return;
    float w = (e < EE) ? ew[e] : 1.0f;
    int t = g_tgt[e];
    atomicAdd(&g_deg[t], w);
    atomicAdd(&g_cnt[t], 1);
}

__global__ void k_dinv() {
    int i = blockIdx.x * blockDim.x + threadIdx.x;
    if (i < NN) {
        float d = g_deg[i];
        g_deg[i] = (d > 0.f) ? (1.0f / sqrtf(d)) : 0.f;
    }
}

__global__ void k_wn(const float* __restrict__ ew) {
    int e = blockIdx.x * blockDim.x + threadIdx.x;
    if (e >= ETOT) return;
    float w = (e < EE) ? ew[e] : 1.0f;
    g_wn[e] = g_deg[g_src[e]] * w * g_deg[g_tgt[e]];  // g_deg holds dinv now
}

__global__ void k_scan() {
    __shared__ int part[1024];
    int tid = threadIdx.x;
    const int CH = CDIV(NN, 1024);
    int s0 = tid * CH;
    int sum = 0;
    for (int i = 0; i < CH; i++) {
        int idx = s0 + i;
        if (idx < NN) sum += g_cnt[idx];
    }
    part[tid] = sum;
    __syncthreads();
    if (tid == 0) {
        int run = 0;
        for (int i = 0; i < 1024; i++) { int t = part[i]; part[i] = run; run += t; }
        g_indptr[NN] = run;
    }
    __syncthreads();
    int off = part[tid];
    for (int i = 0; i < CH; i++) {
        int idx = s0 + i;
        if (idx < NN) {
            g_indptr[idx] = off;
            g_cursor[idx] = off;
            off += g_cnt[idx];
        }
    }
}

__global__ void k_bucket() {
    int e = blockIdx.x * blockDim.x + threadIdx.x;
    if (e >= ETOT) return;
    int t = g_tgt[e];
    int p = atomicAdd(&g_cursor[t], 1);
    g_bsrc[p] = g_src[e];
    g_bw[p]   = g_wn[e];
}

__global__ void k_initW(const float* __restrict__ W0) {
    int idx = blockIdx.x * blockDim.x + threadIdx.x;
    if (idx >= LL * BATCH * DD * DD) return;
    int c  = idx / (BATCH * DD * DD);
    int ij = idx % (DD * DD);
    g_W[idx] = W0[c * DD * DD + ij];
}

__global__ void k_transpose(const float* __restrict__ wih, const float* __restrict__ whh) {
    int idx = blockIdx.x * blockDim.x + threadIdx.x;
    if (idx >= LL * G3 * DD) return;
    int c = idx / (G3 * DD);
    int r = idx % (G3 * DD);
    int q = r / DD;
    int k = r % DD;
    g_wihT[(c * DD + k) * G3 + q] = wih[idx];
    g_whhT[(c * DD + k) * G3 + q] = whh[idx];
}

// ---------------- batched upfront kernels ----------------

// PX[t][b][n] = sum_j wn_j * x[b][t][src_j]   (pure weighted gather; warp per node)
__global__ void k_prop_x(const float* __restrict__ x) {
    int warp = threadIdx.x >> 5, lane = threadIdx.x & 31;
    int n = blockIdx.x * 8 + warp;
    int b = blockIdx.y;
    int t = blockIdx.z;
    if (n >= NN) return;
    int s = g_indptr[n], e = g_indptr[n + 1];
    const float* xb = x + ((long)b * TT + t) * NN * DD;
    float4 acc = make_float4(0.f, 0.f, 0.f, 0.f);
    for (int j = s; j < e; j++) {
        int   src = g_bsrc[j];
        float w   = g_bw[j];
        float4 v = *(const float4*)&xb[(long)src * DD + lane * 4];
        acc.x += w * v.x; acc.y += w * v.y; acc.z += w * v.z; acc.w += w * v.w;
    }
    *(float4*)&g_px[(((long)t * BATCH + b) * NN + n) * DD + lane * 4] = acc;
}

// PA[b][n] = sum_j wn_j * act[b][src_j]
__global__ void k_prop_a() {
    int warp = threadIdx.x >> 5, lane = threadIdx.x & 31;
    int n = blockIdx.x * 8 + warp;
    int b = blockIdx.y;
    if (n >= NN) return;
    int s = g_indptr[n], e = g_indptr[n + 1];
    const float* ab = g_act + (long)b * NN * DD;
    float4 acc = make_float4(0.f, 0.f, 0.f, 0.f);
    for (int j = s; j < e; j++) {
        int   src = g_bsrc[j];
        float w   = g_bw[j];
        float4 v = *(const float4*)&ab[(long)src * DD + lane * 4];
        acc.x += w * v.x; acc.y += w * v.y; acc.z += w * v.z; acc.w += w * v.w;
    }
    *(float4*)&g_pa[((long)b * NN + n) * DD + lane * 4] = acc;
}

// layer-0 scores for ALL (t,b): sc0[(t*2+b)][n] = dot(x[b][t][n], p0)
__global__ void k_scores_all(const float* __restrict__ x, const float* __restrict__ pc) {
    int pair = blockIdx.y;            // t*2 + b
    int t = pair >> 1, b = pair & 1;
    int warp = threadIdx.x >> 5, lane = threadIdx.x & 31;
    int node = blockIdx.x * 8 + warp;
    if (node >= NN) return;
    const float4* xr = (const float4*)(x + (((long)b * TT + t) * NN + node) * DD);
    float4 xv = xr[lane];
    float4 pv = ((const float4*)pc)[lane];
    float s = xv.x * pv.x + xv.y * pv.y + xv.z * pv.z + xv.w * pv.w;
    #pragma unroll
    for (int o = 16; o; o >>= 1) s += __shfl_down_sync(0xffffffffu, s, o);
    if (lane == 0) g_sc0[(long)pair * NN + node] = s;
}

// ---------------- per-step kernels ----------------

// Exact top-128 via 4-pass byte radix-select + bitonic sort of candidates.
// Matches jax.lax.top_k semantics: sorted desc, ties -> smallest index first.
// One block per (pair); scores/topidx/toptv indexed by blockIdx.x.
#define CAND_MAX 512
__global__ void k_topk(const float* __restrict__ pc,
                       const float* __restrict__ scores,
                       int* __restrict__ topidx, float* __restrict__ toptv) {
    int pair = blockIdx.x;
    scores += (long)pair * NN;
    topidx += pair * DD;
    toptv  += pair * DD;
    int tid = threadIdx.x;
    __shared__ unsigned s_u[NN];
    __shared__ int hist[256];
    __shared__ int suf[256];
    __shared__ unsigned long long cand[CAND_MAX];
    __shared__ int sh_v, sh_krem, sh_cnt;
    __shared__ unsigned sh_prefix;
    __shared__ float s_invn;

    if (tid == 0) {
        float acc = 0.f;
        for (int i = 0; i < DD; i++) { float v = pc[i]; acc += v * v; }
        s_invn = 1.0f / sqrtf(acc);
        sh_krem = DD;
        sh_prefix = 0u;
        sh_cnt = 0;
    }
    for (int i = tid; i < NN; i += 1024) {
        unsigned u = __float_as_uint(scores[i]);
        u = (u & 0x80000000u) ? ~u : (u | 0x80000000u);
        s_u[i] = u;
    }
    __syncthreads();

    for (int pass = 0; pass < 4; pass++) {
        int shift = 24 - 8 * pass;
        if (tid < 256) hist[tid] = 0;
        __syncthreads();
        unsigned pref = sh_prefix;
        for (int i = tid; i < NN; i += 1024) {
            unsigned u = s_u[i];
            bool m = (pass == 0) || ((u >> (shift + 8)) == pref);
            if (m) atomicAdd(&hist[(u >> shift) & 0xFF], 1);
        }
        __syncthreads();
        if (tid < 256) suf[tid] = hist[tid];
        __syncthreads();
        for (int off = 1; off < 256; off <<= 1) {
            int v = 0;
            if (tid < 256 && tid + off < 256) v = suf[tid + off];
            __syncthreads();
            if (tid < 256) suf[tid] += v;
            __syncthreads();
        }
        if (tid < 256) {
            int gt = suf[tid] - hist[tid];
            int krem = sh_krem;
            if (gt < krem && gt + hist[tid] >= krem) sh_v = tid;
        }
        __syncthreads();
        if (tid == 0) {
            int v = sh_v;
            sh_krem -= (suf[v] - hist[v]);
            sh_prefix = (sh_prefix << 8) | (unsigned)v;
        }
        __syncthreads();
    }
    unsigned uthr = sh_prefix;

    for (int i = tid; i < NN; i += 1024) {
        unsigned u = s_u[i];
        if (u >= uthr) {
            int p = atomicAdd(&sh_cnt, 1);
            if (p < CAND_MAX)
                cand[p] = ((unsigned long long)u << 32) |
                          (unsigned long long)(0xFFFFFFFFu - (unsigned)i);
        }
    }
    __syncthreads();
    int cnt = min(sh_cnt, CAND_MAX);
    int P = 256; while (P < cnt) P <<= 1;
    for (int i = cnt + tid; i < P; i += 1024) cand[i] = 0ULL;
    __syncthreads();

    for (int k2 = 2; k2 <= P; k2 <<= 1) {
        for (int j = k2 >> 1; j > 0; j >>= 1) {
            for (int i = tid; i < P; i += 1024) {
                int l = i ^ j;
                if (l > i) {
                    unsigned long long a = cand[i], bb = cand[l];
                    bool desc = ((i & k2) == 0);
                    if (desc ? (a < bb) : (a > bb)) { cand[i] = bb; cand[l] = a; }
                }
            }
            __syncthreads();
        }
    }

    if (tid < DD) {
        unsigned long long key = cand[tid];
        unsigned u = (unsigned)(key >> 32);
        u = (u & 0x80000000u) ? (u & 0x7FFFFFFFu) : ~u;
        float f = __uint_as_float(u);
        int idx = (int)(0xFFFFFFFFu - (unsigned)(key & 0xFFFFFFFFu));
        topidx[tid] = idx;
        toptv [tid] = tanhf(f * s_invn);
    }
}

// GRU cell: each block handles 4 columns (j) of W[b]; thread h = hidden index.
__global__ void k_gru(const float* __restrict__ in, long bstride, int c,
                      const int* __restrict__ topidx, const float* __restrict__ toptv,
                      const float* __restrict__ bih, const float* __restrict__ bhh) {
    int b = blockIdx.y;
    int h = threadIdx.x;
    int colBase = blockIdx.x * 4;
    __shared__ float xg[4][DD];
    __shared__ float hg[4][DD];
    float* Wl = g_W + ((long)c * BATCH + b) * DD * DD;
    #pragma unroll
    for (int cc = 0; cc < 4; cc++) {
        int col = colBase + cc;
        int node = topidx[b * DD + col];
        float tv = toptv[b * DD + col];
        xg[cc][h] = in[(long)b * bstride + (long)node * DD + h] * tv;
        hg[cc][h] = Wl[h * DD + col];
    }
    __syncthreads();
    const float* WI = g_wihT + (long)c * DD * G3;
    const float* WH = g_whhT + (long)c * DD * G3;
    float ir[4] = {0}, iz[4] = {0}, in_[4] = {0};
    float hr[4] = {0}, hz[4] = {0}, hn[4] = {0};
    for (int k = 0; k < DD; k++) {
        float a0 = WI[k * G3 + h], a1 = WI[k * G3 + 128 + h], a2 = WI[k * G3 + 256 + h];
        float b0 = WH[k * G3 + h], b1 = WH[k * G3 + 128 + h], b2 = WH[k * G3 + 256 + h];
        #pragma unroll
        for (int cc = 0; cc < 4; cc++) {
            float xv = xg[cc][k], hv = hg[cc][k];
            ir[cc] += xv * a0; iz[cc] += xv * a1; in_[cc] += xv * a2;
            hr[cc] += hv * b0; hz[cc] += hv * b1; hn[cc] += hv * b2;
        }
    }
    float bi0 = bih[h], bi1 = bih[128 + h], bi2 = bih[256 + h];
    float bh0 = bhh[h], bh1 = bhh[128 + h], bh2 = bhh[256 + h];
    #pragma unroll
    for (int cc = 0; cc < 4; cc++) {
        float r = 1.f / (1.f + expf(-((ir[cc] + bi0) + (hr[cc] + bh0))));
        float z = 1.f / (1.f + expf(-((iz[cc] + bi1) + (hz[cc] + bh1))));
        float n = tanhf((in_[cc] + bi2) + r * (hn[cc] + bh2));
        float hnew = (1.f - z) * n + z * hg[cc][h];
        Wl[h * DD + colBase + cc] = hnew;
    }
}

// out[b] = relu(in[b] @ W[c][b] + bias); optional fused next-layer scores epilogue.
// X tile stored transposed + XOR-swizzled (broadcast float4 LDS for X).
__global__ void k_gemm_fused(const float* __restrict__ in, long bstride, int c,
                             const float* __restrict__ bias,
                             float* __restrict__ outp, long obstride,
                             const float* __restrict__ pc, float* __restrict__ scoresOut) {
    int b = blockIdx.y;
    const float* W = g_W + ((long)c * BATCH + b) * DD * DD;
    const float* X = in + (long)b * bstride;
    int rowBase = blockIdx.x * 32;
    int tid = threadIdx.x;
    int ty = tid >> 5, tx = tid & 31;
    __shared__ float xs[32 * 32];   // [k][row], row-groups swizzled by k
    __shared__ float ws[32 * DD];
    float4 acc[4];
    #pragma unroll
    for (int i = 0; i < 4; i++) acc[i] = make_float4(0.f, 0.f, 0.f, 0.f);

    for (int kt = 0; kt < 4; kt++) {
        {
            int r  = tid >> 3;
            int c8 = tid & 7;
            int row = rowBase + r;
            float4 xv = make_float4(0.f, 0.f, 0.f, 0.f);
            if (row < NN)
                xv = *(const float4*)&X[(long)row * DD + kt * 32 + c8 * 4];
            int g = r >> 2, rl = r & 3;
            float v[4] = {xv.x, xv.y, xv.z, xv.w};
            #pragma unroll
            for (int i = 0; i < 4; i++) {
                int k = c8 * 4 + i;
                xs[k * 32 + (((g ^ (k & 7)) << 2) | rl)] = v[i];
            }
        }
        const float4* W4 = (const float4*)(W + kt * 32 * DD);
        float4* ws4 = (float4*)ws;
        for (int l = tid; l < 32 * 32; l += 256) ws4[l] = W4[l];
        __syncthreads();
        #pragma unroll
        for (int k = 0; k < 32; k++) {
            float4 wv = ((float4*)ws)[k * 32 + tx];
            float4 xv = *(float4*)&xs[k * 32 + ((ty ^ (k & 7)) << 2)];
            acc[0].x += xv.x * wv.x; acc[0].y += xv.x * wv.y; acc[0].z += xv.x * wv.z; acc[0].w += xv.x * wv.w;
            acc[1].x += xv.y * wv.x; acc[1].y += xv.y * wv.y; acc[1].z += xv.y * wv.z; acc[1].w += xv.y * wv.w;
            acc[2].x += xv.z * wv.x; acc[2].y += xv.z * wv.y; acc[2].z += xv.z * wv.z; acc[2].w += xv.z * wv.w;
            acc[3].x += xv.w * wv.x; acc[3].y += xv.w * wv.y; acc[3].z += xv.w * wv.z; acc[3].w += xv.w * wv.w;
        }
        __syncthreads();
    }
    float4 bv = ((const float4*)bias)[tx];
    #pragma unroll
    for (int i = 0; i < 4; i++) {
        int row = rowBase + ty * 4 + i;
        if (row < NN) {
            acc[i].x = fmaxf(acc[i].x + bv.x, 0.f);
            acc[i].y = fmaxf(acc[i].y + bv.y, 0.f);
            acc[i].z = fmaxf(acc[i].z + bv.z, 0.f);
            acc[i].w = fmaxf(acc[i].w + bv.w, 0.f);
            *(float4*)&outp[(long)b * obstride + (long)row * DD + tx * 4] = acc[i];
        }
    }
    if (scoresOut) {
        float4 pv = ((const float4*)pc)[tx];
        #pragma unroll
        for (int i = 0; i < 4; i++) {
            int row = rowBase + ty * 4 + i;
            if (row < NN) {   // uniform across warp
                float s = acc[i].x * pv.x + acc[i].y * pv.y + acc[i].z * pv.z + acc[i].w * pv.w;
                #pragma unroll
                for (int o = 16; o; o >>= 1) s += __shfl_down_sync(0xffffffffu, s, o);
                if (tx == 0) scoresOut[(long)b * NN + row] = s;
            }
        }
    }
}

// ---------------- launcher ----------------
extern "C" void kernel_launch(void* const* d_in, const int* in_sizes, int n_in,
                              void* d_out, int out_size) {
    const float* x    = (const float*)d_in[0];
    const void*  ei   = d_in[1];
    const float* ew   = (const float*)d_in[2];
    const float* W0   = (const float*)d_in[3];
    const float* p    = (const float*)d_in[4];
    const float* wih  = (const float*)d_in[5];
    const float* whh  = (const float*)d_in[6];
    const float* bih  = (const float*)d_in[7];
    const float* bhh  = (const float*)d_in[8];
    const float* bias = (const float*)d_in[9];
    float* out = (float*)d_out;

    float *p_act, *p_px, *p_pa, *p_sc0, *p_sc1, *p_tv0, *p_tv1;
    int *p_ti0, *p_ti1;
    cudaGetSymbolAddress((void**)&p_act, g_act);
    cudaGetSymbolAddress((void**)&p_px,  g_px);
    cudaGetSymbolAddress((void**)&p_pa,  g_pa);
    cudaGetSymbolAddress((void**)&p_sc0, g_sc0);
    cudaGetSymbolAddress((void**)&p_sc1, g_sc1);
    cudaGetSymbolAddress((void**)&p_ti0, g_ti0);
    cudaGetSymbolAddress((void**)&p_tv0, g_tv0);
    cudaGetSymbolAddress((void**)&p_ti1, g_ti1);
    cudaGetSymbolAddress((void**)&p_tv1, g_tv1);

    // graph preprocessing (once per launch)
    k_detect<<<1, 256>>>(ei);
    k_zero<<<CDIV(NN, 256), 256>>>();
    k_convert<<<CDIV(ETOT, 256), 256>>>(ei);
    k_deg<<<CDIV(ETOT, 256), 256>>>(ew);
    k_dinv<<<CDIV(NN, 256), 256>>>();
    k_wn<<<CDIV(ETOT, 256), 256>>>(ew);
    k_scan<<<1, 1024>>>();
    k_bucket<<<CDIV(ETOT, 256), 256>>>();
    k_initW<<<CDIV(LL * BATCH * DD * DD, 256), 256>>>(W0);
    k_transpose<<<CDIV(LL * G3 * DD, 256), 256>>>(wih, whh);

    // propagate x for all timesteps (linearity: P(X@W) = (PX)@W), batched
    k_prop_x<<<dim3(CDIV(NN, 8), BATCH, TT), 256>>>(x);
    // layer-0 scores + topk for all timesteps, batched
    k_scores_all<<<dim3(CDIV(NN, 8), TT * BATCH), 256>>>(x, p);
    k_topk<<<TT * BATCH, 1024>>>(p, p_sc0, p_ti0, p_tv0);

    for (int t = 0; t < TT; t++) {
        // layer 0: evolve W0, then act_t = relu(PX_t @ W0 + b0), fused layer-1 scores
        k_gru<<<dim3(DD / 4, BATCH), DD>>>(x + (long)t * NN * DD, (long)TT * NN * DD, 0,
                                           p_ti0 + t * BATCH * DD, p_tv0 + t * BATCH * DD,
                                           bih, bhh);
        k_gemm_fused<<<dim3(CDIV(NN, 32), BATCH), 256>>>(
            p_px + (long)t * BATCH * NN * DD, (long)NN * DD, 0,
            bias, p_act, (long)NN * DD, p + DD, p_sc1);
        // layer 1: topk + evolve W1 (GEMM/prop only needed at t = T-1)
        k_topk<<<BATCH, 1024>>>(p + DD, p_sc1, p_ti1, p_tv1);
        k_gru<<<dim3(DD / 4, BATCH), DD>>>(p_act, (long)NN * DD, 1,
                                           p_ti1, p_tv1, bih + G3, bhh + G3);
    }
    // final output: out = relu((P act_7) @ W1 + b1)
    k_prop_a<<<dim3(CDIV(NN, 8), BATCH), 256>>>();
    k_gemm_fused<<<dim3(CDIV(NN, 32), BATCH), 256>>>(
        p_pa, (long)NN * DD, 1, bias + DD, out, (long)NN * DD, nullptr, nullptr);
}